// round 1
// baseline (speedup 1.0000x reference)
#include <cuda_runtime.h>
#include <cstdint>

#define BB 16
#define NPTS 4096

// ---------------- scratch (static device globals; no allocation) ----------------
__device__ float g_xyz1[BB * NPTS * 3];
__device__ float g_feat1[BB * 6 * NPTS];
__device__ int   g_sidx1[BB * 512];
__device__ float g_xyz2[BB * 512 * 3];
__device__ float g_grp1[BB * 9 * 512 * 32];
__device__ float g_h1[BB * 64 * 512 * 32];
__device__ float g_feat2[BB * 128 * 512];
__device__ int   g_sidx2[BB * 64];
__device__ float g_xyz3[BB * 64 * 3];
__device__ float g_grp2[BB * 131 * 64 * 64];
__device__ float g_h2[BB * 128 * 64 * 64];
__device__ float g_feat3[BB * 256 * 64];
__device__ int   g_sidx3[BB * 1];
__device__ float g_xyz4[BB * 3];
__device__ float g_grp3[BB * 259 * 64];
__device__ float g_h3[BB * 512 * 64];
__device__ float g_feat4[BB * 1024];
__device__ float g_c1[BB * 1024];
__device__ float g_c2[BB * 512];
__device__ float g_c3[BB * 128];

// ---------------- split pointcloud into xyz [B,N,3] and feats [B,6,N] ----------------
__global__ void split_kernel(const float* __restrict__ pc,
                             float* __restrict__ xyz, float* __restrict__ feat) {
    int idx = blockIdx.x * blockDim.x + threadIdx.x;
    if (idx >= BB * NPTS) return;
    int b = idx / NPTS, n = idx % NPTS;
    const float* p = pc + (size_t)idx * 9;
    xyz[idx * 3 + 0] = p[0];
    xyz[idx * 3 + 1] = p[1];
    xyz[idx * 3 + 2] = p[2];
#pragma unroll
    for (int c = 0; c < 6; c++)
        feat[((size_t)b * 6 + c) * NPTS + n] = p[3 + c];
}

// ---------------- furthest point sampling (exact JAX arithmetic) ----------------
// one block (1024 threads) per batch; dist in registers; argmax w/ first-index tiebreak
__global__ void fps_kernel(const float* __restrict__ xyz, int N, int npoint,
                           int* __restrict__ out) {
    const int b = blockIdx.x;
    const float* px = xyz + (size_t)b * N * 3;
    const int tid = threadIdx.x;
    const int ITEMS = 4;  // covers N <= 4096 at 1024 threads

    float lx[ITEMS], ly[ITEMS], lz[ITEMS], ld[ITEMS];
#pragma unroll
    for (int i = 0; i < ITEMS; i++) {
        int n = tid + i * 1024;
        if (n < N) {
            lx[i] = px[n * 3 + 0];
            ly[i] = px[n * 3 + 1];
            lz[i] = px[n * 3 + 2];
            ld[i] = 1e10f;
        } else {
            ld[i] = -1.0f;
        }
    }

    __shared__ int s_far;
    __shared__ float swv[32];
    __shared__ int swi[32];
    if (tid == 0) s_far = 0;
    __syncthreads();

    for (int it = 0; it < npoint; it++) {
        int far = s_far;
        if (tid == 0) out[b * npoint + it] = far;
        float cx = px[far * 3 + 0];
        float cy = px[far * 3 + 1];
        float cz = px[far * 3 + 2];

        float bv = -1.0f;
        int bi = 0;
#pragma unroll
        for (int i = 0; i < ITEMS; i++) {
            int n = tid + i * 1024;
            if (n < N) {
                float dx = __fsub_rn(lx[i], cx);
                float dy = __fsub_rn(ly[i], cy);
                float dz = __fsub_rn(lz[i], cz);
                float d = __fadd_rn(__fadd_rn(__fmul_rn(dx, dx), __fmul_rn(dy, dy)),
                                    __fmul_rn(dz, dz));
                float nd = fminf(ld[i], d);
                ld[i] = nd;
                if (nd > bv) { bv = nd; bi = n; }  // ascending n -> first-max kept
            }
        }
        // warp reduce: max val, smaller index on tie
#pragma unroll
        for (int off = 16; off; off >>= 1) {
            float ov = __shfl_xor_sync(0xffffffffu, bv, off);
            int oi = __shfl_xor_sync(0xffffffffu, bi, off);
            if (ov > bv || (ov == bv && oi < bi)) { bv = ov; bi = oi; }
        }
        if ((tid & 31) == 0) { swv[tid >> 5] = bv; swi[tid >> 5] = bi; }
        __syncthreads();
        if (tid < 32) {
            float mv = swv[tid];
            int mi = swi[tid];
#pragma unroll
            for (int off = 16; off; off >>= 1) {
                float ov = __shfl_xor_sync(0xffffffffu, mv, off);
                int oi = __shfl_xor_sync(0xffffffffu, mi, off);
                if (ov > mv || (ov == mv && oi < mi)) { mv = ov; mi = oi; }
            }
            if (tid == 0) s_far = mi;
        }
        __syncthreads();
    }
}

// ---------------- ball query + gather/group (exact JAX arithmetic for compare) ----
// grid (S, B), block 128. warp0 scans all N points in index order, collects first-K
// within radius, pads with first hit (0 if none). then all threads gather grouped tensor.
__global__ void bq_group_kernel(const float* __restrict__ xyz, const int* __restrict__ sidx,
                                const float* __restrict__ feats,
                                float* __restrict__ new_xyz, float* __restrict__ grp,
                                int N, int S, int K, int Cf, float r2) {
    const int b = blockIdx.y, s = blockIdx.x;
    const float* px = xyz + (size_t)b * N * 3;
    const int ci = sidx[b * S + s];
    const float cx = px[ci * 3 + 0];
    const float cy = px[ci * 3 + 1];
    const float cz = px[ci * 3 + 2];
    const int tid = threadIdx.x;

    __shared__ int sIdx[64];

    if (tid == 0) {
        new_xyz[((size_t)b * S + s) * 3 + 0] = cx;
        new_xyz[((size_t)b * S + s) * 3 + 1] = cy;
        new_xyz[((size_t)b * S + s) * 3 + 2] = cz;
    }

    if (tid < 32) {
        int cnt = 0, first = -1;
        for (int base = 0; base < N; base += 32) {
            int j = base + tid;
            bool pred = false;
            if (j < N) {
                float dx = __fsub_rn(cx, px[j * 3 + 0]);
                float dy = __fsub_rn(cy, px[j * 3 + 1]);
                float dz = __fsub_rn(cz, px[j * 3 + 2]);
                float d2 = __fadd_rn(__fadd_rn(__fmul_rn(dx, dx), __fmul_rn(dy, dy)),
                                     __fmul_rn(dz, dz));
                pred = (d2 < r2);
            }
            unsigned m = __ballot_sync(0xffffffffu, pred);
            if (first < 0 && m) first = base + __ffs(m) - 1;
            if (pred) {
                int pos = cnt + __popc(m & ((1u << tid) - 1u));
                if (pos < K) sIdx[pos] = j;
            }
            cnt += __popc(m);
            if (cnt >= K) break;
        }
        int fillv = (first < 0) ? 0 : first;
        for (int k = cnt + tid; k < K; k += 32) sIdx[k] = fillv;
    }
    __syncthreads();

    const int C = 3 + Cf;
    const size_t SK = (size_t)S * K;
    const size_t pbase = (size_t)s * K;
    for (int e = tid; e < C * K; e += blockDim.x) {
        int ch = e / K, k = e - ch * K;
        int j = sIdx[k];
        float v;
        if (ch == 0)      v = __fsub_rn(px[j * 3 + 0], cx);
        else if (ch == 1) v = __fsub_rn(px[j * 3 + 1], cy);
        else if (ch == 2) v = __fsub_rn(px[j * 3 + 2], cz);
        else              v = feats[((size_t)b * Cf + (ch - 3)) * N + j];
        grp[((size_t)b * C + ch) * SK + pbase + k] = v;
    }
}

// ---------------- conv1x1 + BN(scale,bias) + ReLU (tiled GEMM) ----------------
// out[b,o,p] = relu(g[o]*sum_c W[o,c]*x[b,c,p] + bias[o])
// grid (ceil(P/32), ceil(Cout/32), B), block 256 = 32p x 8oy, 4 o's per thread
__global__ void conv_bn_relu_kernel(const float* __restrict__ x, const float* __restrict__ W,
                                    const float* __restrict__ g, const float* __restrict__ bi,
                                    float* __restrict__ out, int Cin, int Cout, int P) {
    const int b = blockIdx.z;
    const int p0 = blockIdx.x * 32;
    const int o0 = blockIdx.y * 32;
    __shared__ float xs[32][32];
    __shared__ float ws[32][33];
    const int tid = threadIdx.x;
    const int tx = tid & 31, ty = tid >> 5;
    float acc[4] = {0.f, 0.f, 0.f, 0.f};
    const float* xb = x + (size_t)b * Cin * P;

    for (int c0 = 0; c0 < Cin; c0 += 32) {
#pragma unroll
        for (int s = 0; s < 4; s++) {
            int e = tid + s * 256;
            int r = e >> 5, i = e & 31;
            int cc = c0 + r, pp = p0 + i;
            xs[r][i] = (cc < Cin && pp < P) ? xb[(size_t)cc * P + pp] : 0.f;
            int oo = o0 + r, cw = c0 + i;
            ws[r][i] = (oo < Cout && cw < Cin) ? W[(size_t)oo * Cin + cw] : 0.f;
        }
        __syncthreads();
#pragma unroll
        for (int c = 0; c < 32; c++) {
            float xv = xs[c][tx];
#pragma unroll
            for (int j = 0; j < 4; j++)
                acc[j] = fmaf(ws[ty + j * 8][c], xv, acc[j]);
        }
        __syncthreads();
    }

    int pp = p0 + tx;
    if (pp < P) {
        float* ob = out + (size_t)b * Cout * P;
#pragma unroll
        for (int j = 0; j < 4; j++) {
            int oo = o0 + ty + j * 8;
            if (oo < Cout) {
                float v = fmaf(acc[j], g[oo], bi[oo]);
                ob[(size_t)oo * P + pp] = fmaxf(v, 0.f);
            }
        }
    }
}

// ---------------- conv1x1 + BN + ReLU + max over K (group pooled GEMM) -----------
// out[b,o,s] = max_k relu(g[o]*sum_c W[o,c]*x[b,c,s*K+k] + bias[o])
// grid (B*S, Cout/(OPT*4)), block 256; OPT=256/K; thread=(kx, oy) handles 4 o's.
__global__ void conv_bn_relu_max_kernel(const float* __restrict__ x, const float* __restrict__ W,
                                        const float* __restrict__ g, const float* __restrict__ bi,
                                        float* __restrict__ out,
                                        int Cin, int Cout, int S, int K) {
    const int bs = blockIdx.x;
    const int b = bs / S, s = bs % S;
    const int OPT = 256 / K;
    const int tid = threadIdx.x;
    const int kx = tid % K;
    const int oy = tid / K;
    const int o0 = blockIdx.y * OPT * 4;
    const int SK = S * K;

    __shared__ float hs[64 * 64];  // CT x K, CT=64, K<=64
    __shared__ float red[8];
    const int CT = 64;

    float acc[4] = {0.f, 0.f, 0.f, 0.f};
    const float* xb = x + (size_t)b * Cin * SK + (size_t)s * K;

    for (int c0 = 0; c0 < Cin; c0 += CT) {
        int ctn = min(CT, Cin - c0);
        for (int e = tid; e < ctn * K; e += 256) {
            int c = e / K, k = e - c * K;
            hs[c * K + k] = xb[(size_t)(c0 + c) * SK + k];
        }
        __syncthreads();
        for (int c = 0; c < ctn; c++) {
            float hv = hs[c * K + kx];
#pragma unroll
            for (int j = 0; j < 4; j++) {
                int oo = o0 + oy + j * OPT;
                acc[j] = fmaf(W[(size_t)oo * Cin + c0 + c], hv, acc[j]);
            }
        }
        __syncthreads();
    }

    const int wid = tid >> 5;
    const int wpk = K / 32;  // warps per k-group (1 or 2)
    for (int j = 0; j < 4; j++) {
        int oo = o0 + oy + j * OPT;
        float v = fmaxf(fmaf(acc[j], g[oo], bi[oo]), 0.f);
#pragma unroll
        for (int off = 16; off; off >>= 1)
            v = fmaxf(v, __shfl_xor_sync(0xffffffffu, v, off));
        if ((tid & 31) == 0) red[wid] = v;
        __syncthreads();
        if (tid < OPT) {
            float m = red[tid * wpk];
            if (wpk == 2) m = fmaxf(m, red[tid * wpk + 1]);
            int o = o0 + tid + j * OPT;
            if (o < Cout) out[((size_t)b * Cout + o) * S + s] = m;
        }
        __syncthreads();
    }
}

// ---------------- dense layer on [B, Cin] vectors (classifier head) ----------------
__global__ void dense_kernel(const float* __restrict__ x, const float* __restrict__ W,
                             const float* __restrict__ g, const float* __restrict__ bi,
                             float* __restrict__ out, int Cin, int Cout, int do_relu) {
    const int b = blockIdx.x;
    const int o = blockIdx.y * 8 + (threadIdx.x >> 5);
    const int lane = threadIdx.x & 31;
    if (o >= Cout) return;
    const float* xb = x + (size_t)b * Cin;
    float acc = 0.f;
    for (int c = lane; c < Cin; c += 32)
        acc = fmaf(W[(size_t)o * Cin + c], xb[c], acc);
#pragma unroll
    for (int off = 16; off; off >>= 1)
        acc += __shfl_xor_sync(0xffffffffu, acc, off);
    if (lane == 0) {
        float v = g ? fmaf(acc, g[o], bi[o]) : (acc + bi[o]);
        if (do_relu) v = fmaxf(v, 0.f);
        out[(size_t)b * Cout + o] = v;
    }
}

// ---------------- launch ----------------
extern "C" void kernel_launch(void* const* d_in, const int* in_sizes, int n_in,
                              void* d_out, int out_size) {
    const float* pc = (const float*)d_in[0];
    const float* saw[3][2];
    const float* sag[3][2];
    const float* sab[3][2];
    for (int sm = 0; sm < 3; sm++)
        for (int l = 0; l < 2; l++) {
            int base = 1 + sm * 6 + l * 3;
            saw[sm][l] = (const float*)d_in[base + 0];
            sag[sm][l] = (const float*)d_in[base + 1];
            sab[sm][l] = (const float*)d_in[base + 2];
        }
    const float* clsw[4];
    const float* clsg[3];
    const float* clsb[4];
    for (int l = 0; l < 3; l++) {
        clsw[l] = (const float*)d_in[19 + l * 3 + 0];
        clsg[l] = (const float*)d_in[19 + l * 3 + 1];
        clsb[l] = (const float*)d_in[19 + l * 3 + 2];
    }
    clsw[3] = (const float*)d_in[28];
    clsb[3] = (const float*)d_in[29];

    float *xyz1, *feat1, *xyz2, *grp1, *h1, *feat2, *xyz3, *grp2, *h2, *feat3;
    float *xyz4, *grp3, *h3, *feat4, *c1, *c2, *c3;
    int *sidx1, *sidx2, *sidx3;
    cudaGetSymbolAddress((void**)&xyz1, g_xyz1);
    cudaGetSymbolAddress((void**)&feat1, g_feat1);
    cudaGetSymbolAddress((void**)&sidx1, g_sidx1);
    cudaGetSymbolAddress((void**)&xyz2, g_xyz2);
    cudaGetSymbolAddress((void**)&grp1, g_grp1);
    cudaGetSymbolAddress((void**)&h1, g_h1);
    cudaGetSymbolAddress((void**)&feat2, g_feat2);
    cudaGetSymbolAddress((void**)&sidx2, g_sidx2);
    cudaGetSymbolAddress((void**)&xyz3, g_xyz3);
    cudaGetSymbolAddress((void**)&grp2, g_grp2);
    cudaGetSymbolAddress((void**)&h2, g_h2);
    cudaGetSymbolAddress((void**)&feat3, g_feat3);
    cudaGetSymbolAddress((void**)&sidx3, g_sidx3);
    cudaGetSymbolAddress((void**)&xyz4, g_xyz4);
    cudaGetSymbolAddress((void**)&grp3, g_grp3);
    cudaGetSymbolAddress((void**)&h3, g_h3);
    cudaGetSymbolAddress((void**)&feat4, g_feat4);
    cudaGetSymbolAddress((void**)&c1, g_c1);
    cudaGetSymbolAddress((void**)&c2, g_c2);
    cudaGetSymbolAddress((void**)&c3, g_c3);

    // split
    split_kernel<<<(BB * NPTS + 255) / 256, 256>>>(pc, xyz1, feat1);

    // ---- SA1: N=4096 -> S=512, K=32, r=0.1, C: 9 -> 64 -> 128 ----
    fps_kernel<<<BB, 1024>>>(xyz1, NPTS, 512, sidx1);
    bq_group_kernel<<<dim3(512, BB), 128>>>(xyz1, sidx1, feat1, xyz2, grp1,
                                            NPTS, 512, 32, 6, (float)(0.1 * 0.1));
    conv_bn_relu_kernel<<<dim3(512 * 32 / 32, 2, BB), 256>>>(
        grp1, saw[0][0], sag[0][0], sab[0][0], h1, 9, 64, 512 * 32);
    conv_bn_relu_max_kernel<<<dim3(BB * 512, 128 / 32), 256>>>(
        h1, saw[0][1], sag[0][1], sab[0][1], feat2, 64, 128, 512, 32);

    // ---- SA2: N=512 -> S=64, K=64, r=0.2, C: 131 -> 128 -> 256 ----
    fps_kernel<<<BB, 1024>>>(xyz2, 512, 64, sidx2);
    bq_group_kernel<<<dim3(64, BB), 128>>>(xyz2, sidx2, feat2, xyz3, grp2,
                                           512, 64, 64, 128, (float)(0.2 * 0.2));
    conv_bn_relu_kernel<<<dim3((64 * 64 + 31) / 32, 4, BB), 256>>>(
        grp2, saw[1][0], sag[1][0], sab[1][0], h2, 131, 128, 64 * 64);
    conv_bn_relu_max_kernel<<<dim3(BB * 64, 256 / 16), 256>>>(
        h2, saw[1][1], sag[1][1], sab[1][1], feat3, 128, 256, 64, 64);

    // ---- SA3: N=64 -> S=1, K=64, r=0.4, C: 259 -> 512 -> 1024 ----
    fps_kernel<<<BB, 1024>>>(xyz3, 64, 1, sidx3);
    bq_group_kernel<<<dim3(1, BB), 128>>>(xyz3, sidx3, feat3, xyz4, grp3,
                                          64, 1, 64, 256, (float)(0.4 * 0.4));
    conv_bn_relu_kernel<<<dim3((64 + 31) / 32, 16, BB), 256>>>(
        grp3, saw[2][0], sag[2][0], sab[2][0], h3, 259, 512, 64);
    conv_bn_relu_max_kernel<<<dim3(BB * 1, 1024 / 16), 256>>>(
        h3, saw[2][1], sag[2][1], sab[2][1], feat4, 512, 1024, 1, 64);

    // ---- classifier head on [B, 1024] ----
    dense_kernel<<<dim3(BB, 1024 / 8), 256>>>(feat4, clsw[0], clsg[0], clsb[0], c1, 1024, 1024, 1);
    dense_kernel<<<dim3(BB, 512 / 8), 256>>>(c1, clsw[1], clsg[1], clsb[1], c2, 1024, 512, 1);
    dense_kernel<<<dim3(BB, 128 / 8), 256>>>(c2, clsw[2], clsg[2], clsb[2], c3, 512, 128, 1);
    dense_kernel<<<dim3(BB, (63 + 7) / 8), 256>>>(c3, clsw[3], nullptr, clsb[3],
                                                  (float*)d_out, 128, 63, 0);
}

// round 2
// speedup vs baseline: 1.0736x; 1.0736x over previous
#include <cuda_runtime.h>
#include <cstdint>
#include <math_constants.h>

#define BB 16
#define NPTS 4096

// ---------------- scratch (static device globals; no allocation) ----------------
__device__ float g_xyz1[BB * NPTS * 3];
__device__ float g_feat1[BB * 6 * NPTS];
__device__ int   g_sidx1[BB * 512];
__device__ float g_xyz2[BB * 512 * 3];
__device__ float g_grp1[BB * 9 * 512 * 32];
__device__ float g_h1[BB * 64 * 512 * 32];
__device__ float g_feat2[BB * 128 * 512];
__device__ int   g_sidx2[BB * 64];
__device__ float g_xyz3[BB * 64 * 3];
__device__ float g_grp2[BB * 131 * 64 * 64];
__device__ float g_h2[BB * 128 * 64 * 64];
__device__ float g_feat3[BB * 256 * 64];
__device__ int   g_sidx3[BB * 1];
__device__ float g_xyz4[BB * 3];
__device__ float g_grp3[BB * 259 * 64];
__device__ float g_h3[BB * 512 * 64];
__device__ float g_feat4[BB * 1024];
__device__ float g_c1[BB * 1024];
__device__ float g_c2[BB * 512];
__device__ float g_c3[BB * 128];

// ---------------- split pointcloud into xyz [B,N,3] and feats [B,6,N] ----------------
__global__ void split_kernel(const float* __restrict__ pc,
                             float* __restrict__ xyz, float* __restrict__ feat) {
    int idx = blockIdx.x * blockDim.x + threadIdx.x;
    if (idx >= BB * NPTS) return;
    int b = idx / NPTS, n = idx % NPTS;
    const float* p = pc + (size_t)idx * 9;
    xyz[idx * 3 + 0] = p[0];
    xyz[idx * 3 + 1] = p[1];
    xyz[idx * 3 + 2] = p[2];
#pragma unroll
    for (int c = 0; c < 6; c++)
        feat[((size_t)b * 6 + c) * NPTS + n] = p[3 + c];
}

// ---------------- furthest point sampling (exact JAX arithmetic) ----------------
__global__ void fps_kernel(const float* __restrict__ xyz, int N, int npoint,
                           int* __restrict__ out) {
    const int b = blockIdx.x;
    const float* px = xyz + (size_t)b * N * 3;
    const int tid = threadIdx.x;
    const int ITEMS = 4;

    float lx[ITEMS], ly[ITEMS], lz[ITEMS], ld[ITEMS];
#pragma unroll
    for (int i = 0; i < ITEMS; i++) {
        int n = tid + i * 1024;
        if (n < N) {
            lx[i] = px[n * 3 + 0];
            ly[i] = px[n * 3 + 1];
            lz[i] = px[n * 3 + 2];
            ld[i] = 1e10f;
        } else {
            ld[i] = -1.0f;
        }
    }

    __shared__ int s_far;
    __shared__ float swv[32];
    __shared__ int swi[32];
    if (tid == 0) s_far = 0;
    __syncthreads();

    for (int it = 0; it < npoint; it++) {
        int far = s_far;
        if (tid == 0) out[b * npoint + it] = far;
        float cx = px[far * 3 + 0];
        float cy = px[far * 3 + 1];
        float cz = px[far * 3 + 2];

        float bv = -1.0f;
        int bi = 0;
#pragma unroll
        for (int i = 0; i < ITEMS; i++) {
            int n = tid + i * 1024;
            if (n < N) {
                float dx = __fsub_rn(lx[i], cx);
                float dy = __fsub_rn(ly[i], cy);
                float dz = __fsub_rn(lz[i], cz);
                float d = __fadd_rn(__fadd_rn(__fmul_rn(dx, dx), __fmul_rn(dy, dy)),
                                    __fmul_rn(dz, dz));
                float nd = fminf(ld[i], d);
                ld[i] = nd;
                if (nd > bv) { bv = nd; bi = n; }
            }
        }
#pragma unroll
        for (int off = 16; off; off >>= 1) {
            float ov = __shfl_xor_sync(0xffffffffu, bv, off);
            int oi = __shfl_xor_sync(0xffffffffu, bi, off);
            if (ov > bv || (ov == bv && oi < bi)) { bv = ov; bi = oi; }
        }
        if ((tid & 31) == 0) { swv[tid >> 5] = bv; swi[tid >> 5] = bi; }
        __syncthreads();
        if (tid < 32) {
            float mv = swv[tid];
            int mi = swi[tid];
#pragma unroll
            for (int off = 16; off; off >>= 1) {
                float ov = __shfl_xor_sync(0xffffffffu, mv, off);
                int oi = __shfl_xor_sync(0xffffffffu, mi, off);
                if (ov > mv || (ov == mv && oi < mi)) { mv = ov; mi = oi; }
            }
            if (tid == 0) s_far = mi;
        }
        __syncthreads();
    }
}

// ---------------- ball query + gather/group ----------------
__global__ void bq_group_kernel(const float* __restrict__ xyz, const int* __restrict__ sidx,
                                const float* __restrict__ feats,
                                float* __restrict__ new_xyz, float* __restrict__ grp,
                                int N, int S, int K, int Cf, float r2) {
    const int b = blockIdx.y, s = blockIdx.x;
    const float* px = xyz + (size_t)b * N * 3;
    const int ci = sidx[b * S + s];
    const float cx = px[ci * 3 + 0];
    const float cy = px[ci * 3 + 1];
    const float cz = px[ci * 3 + 2];
    const int tid = threadIdx.x;

    __shared__ int sIdx[64];

    if (tid == 0) {
        new_xyz[((size_t)b * S + s) * 3 + 0] = cx;
        new_xyz[((size_t)b * S + s) * 3 + 1] = cy;
        new_xyz[((size_t)b * S + s) * 3 + 2] = cz;
    }

    if (tid < 32) {
        int cnt = 0, first = -1;
        for (int base = 0; base < N; base += 32) {
            int j = base + tid;
            bool pred = false;
            if (j < N) {
                float dx = __fsub_rn(cx, px[j * 3 + 0]);
                float dy = __fsub_rn(cy, px[j * 3 + 1]);
                float dz = __fsub_rn(cz, px[j * 3 + 2]);
                float d2 = __fadd_rn(__fadd_rn(__fmul_rn(dx, dx), __fmul_rn(dy, dy)),
                                     __fmul_rn(dz, dz));
                pred = (d2 < r2);
            }
            unsigned m = __ballot_sync(0xffffffffu, pred);
            if (first < 0 && m) first = base + __ffs(m) - 1;
            if (pred) {
                int pos = cnt + __popc(m & ((1u << tid) - 1u));
                if (pos < K) sIdx[pos] = j;
            }
            cnt += __popc(m);
            if (cnt >= K) break;
        }
        int fillv = (first < 0) ? 0 : first;
        for (int k = cnt + tid; k < K; k += 32) sIdx[k] = fillv;
    }
    __syncthreads();

    const int C = 3 + Cf;
    const size_t SK = (size_t)S * K;
    const size_t pbase = (size_t)s * K;
    for (int e = tid; e < C * K; e += blockDim.x) {
        int ch = e / K, k = e - ch * K;
        int j = sIdx[k];
        float v;
        if (ch == 0)      v = __fsub_rn(px[j * 3 + 0], cx);
        else if (ch == 1) v = __fsub_rn(px[j * 3 + 1], cy);
        else if (ch == 2) v = __fsub_rn(px[j * 3 + 2], cz);
        else              v = feats[((size_t)b * Cf + (ch - 3)) * N + j];
        grp[((size_t)b * C + ch) * SK + pbase + k] = v;
    }
}

// ---------------- SA1 layer1: 9 -> 64 streaming conv + BN + ReLU ----------------
// grid (P/256, B), block 256; one point per thread, all 64 outputs.
__global__ void conv9_kernel(const float* __restrict__ x, const float* __restrict__ W,
                             const float* __restrict__ g, const float* __restrict__ bi,
                             float* __restrict__ out, int P) {
    __shared__ float ws[64 * 9];
    __shared__ float gs[64], bs[64];
    const int tid = threadIdx.x;
    if (tid < 64) { gs[tid] = g[tid]; bs[tid] = bi[tid]; }
    for (int e = tid; e < 576; e += 256) ws[e] = W[e];
    __syncthreads();

    const int b = blockIdx.y;
    const int p = blockIdx.x * 256 + tid;
    const float* xb = x + (size_t)b * 9 * P;
    float xv[9];
#pragma unroll
    for (int c = 0; c < 9; c++) xv[c] = xb[(size_t)c * P + p];
    float* ob = out + (size_t)b * 64 * P;
#pragma unroll 8
    for (int o = 0; o < 64; o++) {
        float a = 0.f;
#pragma unroll
        for (int c = 0; c < 9; c++) a = fmaf(ws[o * 9 + c], xv[c], a);
        ob[(size_t)o * P + p] = fmaxf(fmaf(a, gs[o], bs[o]), 0.f);
    }
}

// ---------------- shared tiled GEMM machinery ----------------
// Tile: 64 outputs (o) x 128 points (p), K-chunk 16, block 256 threads.
// Thread = (warp w, lane px). Warp w owns o rows [o0+8w, o0+8w+8); lane px owns
// p columns {p0+px+32j}. acc[8][4] per thread. ws broadcast per warp (conflict-free).
#define GOT 64
#define GPT 128
#define GCT 16

__device__ __forceinline__ void gemm_tile_loop(
    const float* __restrict__ xb, const float* __restrict__ W,
    int Cin, int P, int o0, int p0, int tid,
    float ws[GCT][68], float xs[GCT][GPT], float acc[8][4]) {
    const int px = tid & 31;
    const int ow = (tid >> 5) * 8;
    for (int c0 = 0; c0 < Cin; c0 += GCT) {
        // stage W tile (c-major, transposed)
#pragma unroll
        for (int l = 0; l < (GCT * GOT) / 256; l++) {
            int e = tid + l * 256;
            int c = e & 15, o = e >> 4;
            int cc = c0 + c;
            ws[c][o] = (cc < Cin) ? W[(size_t)(o0 + o) * Cin + cc] : 0.f;
        }
        // stage x tile
#pragma unroll
        for (int l = 0; l < (GCT * GPT) / 256; l++) {
            int e = tid + l * 256;
            int p = e & 127, c = e >> 7;
            int cc = c0 + c, pp = p0 + p;
            xs[c][p] = (cc < Cin && pp < P) ? xb[(size_t)cc * P + pp] : 0.f;
        }
        __syncthreads();
#pragma unroll
        for (int c = 0; c < GCT; c++) {
            float4 w0 = *reinterpret_cast<const float4*>(&ws[c][ow]);
            float4 w1 = *reinterpret_cast<const float4*>(&ws[c][ow + 4]);
            float wv[8] = {w0.x, w0.y, w0.z, w0.w, w1.x, w1.y, w1.z, w1.w};
            float xv[4];
#pragma unroll
            for (int j = 0; j < 4; j++) xv[j] = xs[c][px + 32 * j];
#pragma unroll
            for (int i = 0; i < 8; i++)
#pragma unroll
                for (int j = 0; j < 4; j++)
                    acc[i][j] = fmaf(wv[i], xv[j], acc[i][j]);
        }
        __syncthreads();
    }
}

__device__ __forceinline__ float warp_max(float v) {
#pragma unroll
    for (int off = 16; off; off >>= 1)
        v = fmaxf(v, __shfl_xor_sync(0xffffffffu, v, off));
    return v;
}

// ---------------- conv1x1 + BN + ReLU (tiled GEMM) ----------------
// grid (ceil(P/128), Cout/64, B)
__global__ __launch_bounds__(256) void gemm_bn_relu_kernel(
    const float* __restrict__ x, const float* __restrict__ W,
    const float* __restrict__ g, const float* __restrict__ bi,
    float* __restrict__ out, int Cin, int Cout, int P) {
    __shared__ float ws[GCT][68];
    __shared__ float xs[GCT][GPT];
    const int b = blockIdx.z;
    const int p0 = blockIdx.x * GPT;
    const int o0 = blockIdx.y * GOT;
    const int tid = threadIdx.x;
    const int px = tid & 31;
    const int ow = (tid >> 5) * 8;

    float acc[8][4];
#pragma unroll
    for (int i = 0; i < 8; i++)
#pragma unroll
        for (int j = 0; j < 4; j++) acc[i][j] = 0.f;

    gemm_tile_loop(x + (size_t)b * Cin * P, W, Cin, P, o0, p0, tid, ws, xs, acc);

    float* ob = out + (size_t)b * Cout * P;
#pragma unroll
    for (int i = 0; i < 8; i++) {
        int o = o0 + ow + i;
        float gv = g[o], bv = bi[o];
#pragma unroll
        for (int j = 0; j < 4; j++) {
            int pp = p0 + px + 32 * j;
            if (pp < P)
                ob[(size_t)o * P + pp] = fmaxf(fmaf(acc[i][j], gv, bv), 0.f);
        }
    }
}

// ---------------- conv1x1 + BN + ReLU + max over K (tiled GEMM + epilogue reduce) --
// x: [B, Cin, S*K]; out: [B, Cout, S]. K in {32, 64}. grid (ceil(S*K/128), Cout/64, B)
__global__ __launch_bounds__(256) void gemm_bn_relu_max_kernel(
    const float* __restrict__ x, const float* __restrict__ W,
    const float* __restrict__ g, const float* __restrict__ bi,
    float* __restrict__ out, int Cin, int Cout, int S, int K) {
    __shared__ float ws[GCT][68];
    __shared__ float xs[GCT][GPT];
    const int b = blockIdx.z;
    const int p0 = blockIdx.x * GPT;
    const int o0 = blockIdx.y * GOT;
    const int tid = threadIdx.x;
    const int px = tid & 31;
    const int ow = (tid >> 5) * 8;
    const int P = S * K;

    float acc[8][4];
#pragma unroll
    for (int i = 0; i < 8; i++)
#pragma unroll
        for (int j = 0; j < 4; j++) acc[i][j] = 0.f;

    gemm_tile_loop(x + (size_t)b * Cin * P, W, Cin, P, o0, p0, tid, ws, xs, acc);

#pragma unroll
    for (int i = 0; i < 8; i++) {
        int o = o0 + ow + i;
        float gv = g[o], bv = bi[o];
        float v[4];
#pragma unroll
        for (int j = 0; j < 4; j++) {
            // P is always a multiple of 32, so validity is uniform over px
            v[j] = (p0 + 32 * j < P) ? fmaf(acc[i][j], gv, bv) : -CUDART_INF_F;
        }
        if (K == 32) {
#pragma unroll
            for (int j = 0; j < 4; j++) {
                float m = warp_max(v[j]);
                int pj = p0 + 32 * j;
                if (px == 0 && pj < P) {
                    int s = pj >> 5;
                    out[((size_t)b * Cout + o) * S + s] = fmaxf(m, 0.f);
                }
            }
        } else {  // K == 64
#pragma unroll
            for (int jj = 0; jj < 2; jj++) {
                float m = warp_max(fmaxf(v[2 * jj], v[2 * jj + 1]));
                int pj = p0 + 64 * jj;
                if (px == 0 && pj < P) {
                    int s = pj >> 6;
                    out[((size_t)b * Cout + o) * S + s] = fmaxf(m, 0.f);
                }
            }
        }
    }
}

// ---------------- dense layer on [B, Cin] vectors (classifier head) ----------------
__global__ void dense_kernel(const float* __restrict__ x, const float* __restrict__ W,
                             const float* __restrict__ g, const float* __restrict__ bi,
                             float* __restrict__ out, int Cin, int Cout, int do_relu) {
    const int b = blockIdx.x;
    const int o = blockIdx.y * 8 + (threadIdx.x >> 5);
    const int lane = threadIdx.x & 31;
    if (o >= Cout) return;
    const float* xb = x + (size_t)b * Cin;
    float acc = 0.f;
    for (int c = lane; c < Cin; c += 32)
        acc = fmaf(W[(size_t)o * Cin + c], xb[c], acc);
#pragma unroll
    for (int off = 16; off; off >>= 1)
        acc += __shfl_xor_sync(0xffffffffu, acc, off);
    if (lane == 0) {
        float v = g ? fmaf(acc, g[o], bi[o]) : (acc + bi[o]);
        if (do_relu) v = fmaxf(v, 0.f);
        out[(size_t)b * Cout + o] = v;
    }
}

// ---------------- launch ----------------
extern "C" void kernel_launch(void* const* d_in, const int* in_sizes, int n_in,
                              void* d_out, int out_size) {
    const float* pc = (const float*)d_in[0];
    const float* saw[3][2];
    const float* sag[3][2];
    const float* sab[3][2];
    for (int sm = 0; sm < 3; sm++)
        for (int l = 0; l < 2; l++) {
            int base = 1 + sm * 6 + l * 3;
            saw[sm][l] = (const float*)d_in[base + 0];
            sag[sm][l] = (const float*)d_in[base + 1];
            sab[sm][l] = (const float*)d_in[base + 2];
        }
    const float* clsw[4];
    const float* clsg[3];
    const float* clsb[4];
    for (int l = 0; l < 3; l++) {
        clsw[l] = (const float*)d_in[19 + l * 3 + 0];
        clsg[l] = (const float*)d_in[19 + l * 3 + 1];
        clsb[l] = (const float*)d_in[19 + l * 3 + 2];
    }
    clsw[3] = (const float*)d_in[28];
    clsb[3] = (const float*)d_in[29];

    float *xyz1, *feat1, *xyz2, *grp1, *h1, *feat2, *xyz3, *grp2, *h2, *feat3;
    float *xyz4, *grp3, *h3, *feat4, *c1, *c2, *c3;
    int *sidx1, *sidx2, *sidx3;
    cudaGetSymbolAddress((void**)&xyz1, g_xyz1);
    cudaGetSymbolAddress((void**)&feat1, g_feat1);
    cudaGetSymbolAddress((void**)&sidx1, g_sidx1);
    cudaGetSymbolAddress((void**)&xyz2, g_xyz2);
    cudaGetSymbolAddress((void**)&grp1, g_grp1);
    cudaGetSymbolAddress((void**)&h1, g_h1);
    cudaGetSymbolAddress((void**)&feat2, g_feat2);
    cudaGetSymbolAddress((void**)&sidx2, g_sidx2);
    cudaGetSymbolAddress((void**)&xyz3, g_xyz3);
    cudaGetSymbolAddress((void**)&grp2, g_grp2);
    cudaGetSymbolAddress((void**)&h2, g_h2);
    cudaGetSymbolAddress((void**)&feat3, g_feat3);
    cudaGetSymbolAddress((void**)&sidx3, g_sidx3);
    cudaGetSymbolAddress((void**)&xyz4, g_xyz4);
    cudaGetSymbolAddress((void**)&grp3, g_grp3);
    cudaGetSymbolAddress((void**)&h3, g_h3);
    cudaGetSymbolAddress((void**)&feat4, g_feat4);
    cudaGetSymbolAddress((void**)&c1, g_c1);
    cudaGetSymbolAddress((void**)&c2, g_c2);
    cudaGetSymbolAddress((void**)&c3, g_c3);

    // split
    split_kernel<<<(BB * NPTS + 255) / 256, 256>>>(pc, xyz1, feat1);

    // ---- SA1: N=4096 -> S=512, K=32, r=0.1, C: 9 -> 64 -> 128 ----
    fps_kernel<<<BB, 1024>>>(xyz1, NPTS, 512, sidx1);
    bq_group_kernel<<<dim3(512, BB), 128>>>(xyz1, sidx1, feat1, xyz2, grp1,
                                            NPTS, 512, 32, 6, (float)(0.1 * 0.1));
    conv9_kernel<<<dim3(512 * 32 / 256, BB), 256>>>(
        grp1, saw[0][0], sag[0][0], sab[0][0], h1, 512 * 32);
    gemm_bn_relu_max_kernel<<<dim3(512 * 32 / GPT, 128 / GOT, BB), 256>>>(
        h1, saw[0][1], sag[0][1], sab[0][1], feat2, 64, 128, 512, 32);

    // ---- SA2: N=512 -> S=64, K=64, r=0.2, C: 131 -> 128 -> 256 ----
    fps_kernel<<<BB, 1024>>>(xyz2, 512, 64, sidx2);
    bq_group_kernel<<<dim3(64, BB), 128>>>(xyz2, sidx2, feat2, xyz3, grp2,
                                           512, 64, 64, 128, (float)(0.2 * 0.2));
    gemm_bn_relu_kernel<<<dim3(64 * 64 / GPT, 128 / GOT, BB), 256>>>(
        grp2, saw[1][0], sag[1][0], sab[1][0], h2, 131, 128, 64 * 64);
    gemm_bn_relu_max_kernel<<<dim3(64 * 64 / GPT, 256 / GOT, BB), 256>>>(
        h2, saw[1][1], sag[1][1], sab[1][1], feat3, 128, 256, 64, 64);

    // ---- SA3: N=64 -> S=1, K=64, r=0.4, C: 259 -> 512 -> 1024 ----
    fps_kernel<<<BB, 1024>>>(xyz3, 64, 1, sidx3);
    bq_group_kernel<<<dim3(1, BB), 128>>>(xyz3, sidx3, feat3, xyz4, grp3,
                                          64, 1, 64, 256, (float)(0.4 * 0.4));
    gemm_bn_relu_kernel<<<dim3(1, 512 / GOT, BB), 256>>>(
        grp3, saw[2][0], sag[2][0], sab[2][0], h3, 259, 512, 64);
    gemm_bn_relu_max_kernel<<<dim3(1, 1024 / GOT, BB), 256>>>(
        h3, saw[2][1], sag[2][1], sab[2][1], feat4, 512, 1024, 1, 64);

    // ---- classifier head on [B, 1024] ----
    dense_kernel<<<dim3(BB, 1024 / 8), 256>>>(feat4, clsw[0], clsg[0], clsb[0], c1, 1024, 1024, 1);
    dense_kernel<<<dim3(BB, 512 / 8), 256>>>(c1, clsw[1], clsg[1], clsb[1], c2, 1024, 512, 1);
    dense_kernel<<<dim3(BB, 128 / 8), 256>>>(c2, clsw[2], clsg[2], clsb[2], c3, 512, 128, 1);
    dense_kernel<<<dim3(BB, (63 + 7) / 8), 256>>>(c3, clsw[3], nullptr, clsb[3],
                                                  (float*)d_out, 128, 63, 0);
}

// round 3
// speedup vs baseline: 2.0420x; 1.9020x over previous
#include <cuda_runtime.h>
#include <cstdint>
#include <math_constants.h>

#define BB 16
#define NPTS 4096

// ---------------- scratch (static device globals; no allocation) ----------------
__device__ __align__(16) float g_xyz1[BB * NPTS * 3];
__device__ __align__(16) float g_feat1[BB * 6 * NPTS];
__device__ __align__(16) int   g_sidx1[BB * 512];
__device__ __align__(16) float g_xyz2[BB * 512 * 3];
__device__ __align__(16) float g_grp1[BB * 9 * 512 * 32];
__device__ __align__(16) float g_h1[BB * 64 * 512 * 32];
__device__ __align__(16) float g_feat2[BB * 128 * 512];
__device__ __align__(16) int   g_sidx2[BB * 64];
__device__ __align__(16) float g_xyz3[BB * 64 * 3];
__device__ __align__(16) float g_grp2[BB * 131 * 64 * 64];
__device__ __align__(16) float g_h2[BB * 128 * 64 * 64];
__device__ __align__(16) float g_feat3[BB * 256 * 64];
__device__ __align__(16) int   g_sidx3[BB * 1];
__device__ __align__(16) float g_xyz4[BB * 3];
__device__ __align__(16) float g_grp3[BB * 259 * 64];
__device__ __align__(16) float g_h3[BB * 512 * 64];
__device__ __align__(16) float g_feat4[BB * 1024];
__device__ __align__(16) float g_c1[BB * 1024];
__device__ __align__(16) float g_c2[BB * 512];
__device__ __align__(16) float g_c3[BB * 128];
// duplicated weights (for f32x2 broadcast operand), per-layer offsets below
__device__ __align__(16) float g_wdup[1500000];

// offsets (floats) into g_wdup
#define WD0 0          // SA1-L2: 64x128  -> 16384
#define WD1 16384      // SA2-L1: 131x128 -> 33536
#define WD2 49920      // SA2-L2: 128x256 -> 65536
#define WD3 115456     // SA3-L1: 259x512 -> 265216
#define WD4 380672     // SA3-L2: 512x1024-> 1048576  (ends 1429248)

// ---------------- small helpers ----------------
__device__ __forceinline__ uint32_t smem_u32(const void* p) {
    return (uint32_t)__cvta_generic_to_shared(p);
}
__device__ __forceinline__ void cp16(uint32_t dst, const void* src, bool v) {
    asm volatile("cp.async.ca.shared.global [%0], [%1], 16, %2;"
                 :: "r"(dst), "l"(src), "r"(v ? 16 : 0));
}
__device__ __forceinline__ void cp_commit() {
    asm volatile("cp.async.commit_group;");
}
template <int N>
__device__ __forceinline__ void cp_wait() {
    asm volatile("cp.async.wait_group %0;" :: "n"(N));
}
__device__ __forceinline__ void fma2(unsigned long long& d, unsigned long long a,
                                     unsigned long long b) {
    asm("fma.rn.f32x2 %0, %1, %2, %0;" : "+l"(d) : "l"(a), "l"(b));
}
__device__ __forceinline__ float u64lo(unsigned long long v) {
    return __uint_as_float((uint32_t)v);
}
__device__ __forceinline__ float u64hi(unsigned long long v) {
    return __uint_as_float((uint32_t)(v >> 32));
}

// ---------------- weight duplication prep ----------------
// Wd[c][2o] = Wd[c][2o+1] = W[o][c]
__global__ void dup_weights_kernel(const float* __restrict__ W, float* __restrict__ Wd,
                                   int Cin, int Cout) {
    int i = blockIdx.x * 256 + threadIdx.x;
    if (i >= Cin * Cout) return;
    int c = i / Cout, o = i - c * Cout;
    float v = W[(size_t)o * Cin + c];
    float* d = Wd + (size_t)c * (2 * Cout) + 2 * o;
    d[0] = v;
    d[1] = v;
}

// ---------------- split pointcloud into xyz [B,N,3] and feats [B,6,N] --------------
__global__ void split_kernel(const float* __restrict__ pc,
                             float* __restrict__ xyz, float* __restrict__ feat) {
    int idx = blockIdx.x * blockDim.x + threadIdx.x;
    if (idx >= BB * NPTS) return;
    int b = idx / NPTS, n = idx % NPTS;
    const float* p = pc + (size_t)idx * 9;
    xyz[idx * 3 + 0] = p[0];
    xyz[idx * 3 + 1] = p[1];
    xyz[idx * 3 + 2] = p[2];
#pragma unroll
    for (int c = 0; c < 6; c++)
        feat[((size_t)b * 6 + c) * NPTS + n] = p[3 + c];
}

// ---------------- furthest point sampling (exact JAX arithmetic; REDUX reduce) -----
__global__ void fps_kernel(const float* __restrict__ xyz, int N, int npoint,
                           int* __restrict__ out) {
    const int b = blockIdx.x;
    const float* px = xyz + (size_t)b * N * 3;
    const int tid = threadIdx.x;
    const int ITEMS = 4;

    float lx[ITEMS], ly[ITEMS], lz[ITEMS], ld[ITEMS];
#pragma unroll
    for (int i = 0; i < ITEMS; i++) {
        int n = tid + i * 1024;
        if (n < N) {
            lx[i] = px[n * 3 + 0];
            ly[i] = px[n * 3 + 1];
            lz[i] = px[n * 3 + 2];
            ld[i] = 1e10f;
        } else {
            ld[i] = -1.0f;
        }
    }

    __shared__ int s_far;
    __shared__ unsigned sv[32];
    __shared__ unsigned si[32];
    if (tid == 0) s_far = 0;
    __syncthreads();

    for (int it = 0; it < npoint; it++) {
        int far = s_far;
        if (tid == 0) out[b * npoint + it] = far;
        float cx = px[far * 3 + 0];
        float cy = px[far * 3 + 1];
        float cz = px[far * 3 + 2];

        float bv = -1.0f;
        int bi = 0;
#pragma unroll
        for (int i = 0; i < ITEMS; i++) {
            int n = tid + i * 1024;
            if (n < N) {
                float dx = __fsub_rn(lx[i], cx);
                float dy = __fsub_rn(ly[i], cy);
                float dz = __fsub_rn(lz[i], cz);
                float d = __fadd_rn(__fadd_rn(__fmul_rn(dx, dx), __fmul_rn(dy, dy)),
                                    __fmul_rn(dz, dz));
                float nd = fminf(ld[i], d);
                ld[i] = nd;
                if (nd > bv) { bv = nd; bi = n; }  // ascending n -> first-max kept
            }
        }
        // warp reduce via REDUX: dists are nonneg -> float bits are order-preserving
        unsigned ub = (tid < N) ? __float_as_uint(bv) : 0u;
        unsigned wmax = __reduce_max_sync(0xffffffffu, ub);
        unsigned uidx = (tid < N && ub == wmax) ? (unsigned)bi : 0xffffffffu;
        unsigned wimin = __reduce_min_sync(0xffffffffu, uidx);
        if ((tid & 31) == 0) { sv[tid >> 5] = wmax; si[tid >> 5] = wimin; }
        __syncthreads();
        if (tid < 32) {
            unsigned v2 = sv[tid], i2 = si[tid];
            unsigned m2 = __reduce_max_sync(0xffffffffu, v2);
            unsigned ii = (v2 == m2) ? i2 : 0xffffffffu;
            unsigned fi = __reduce_min_sync(0xffffffffu, ii);
            if (tid == 0) s_far = (int)fi;
        }
        __syncthreads();
    }
}

// ---------------- ball query + gather/group ----------------
__global__ void bq_group_kernel(const float* __restrict__ xyz, const int* __restrict__ sidx,
                                const float* __restrict__ feats,
                                float* __restrict__ new_xyz, float* __restrict__ grp,
                                int N, int S, int K, int Cf, float r2) {
    const int b = blockIdx.y, s = blockIdx.x;
    const float* px = xyz + (size_t)b * N * 3;
    const int ci = sidx[b * S + s];
    const float cx = px[ci * 3 + 0];
    const float cy = px[ci * 3 + 1];
    const float cz = px[ci * 3 + 2];
    const int tid = threadIdx.x;

    __shared__ int sIdx[64];

    if (tid == 0) {
        new_xyz[((size_t)b * S + s) * 3 + 0] = cx;
        new_xyz[((size_t)b * S + s) * 3 + 1] = cy;
        new_xyz[((size_t)b * S + s) * 3 + 2] = cz;
    }

    if (tid < 32) {
        int cnt = 0, first = -1;
        for (int base = 0; base < N; base += 32) {
            int j = base + tid;
            bool pred = false;
            if (j < N) {
                float dx = __fsub_rn(cx, px[j * 3 + 0]);
                float dy = __fsub_rn(cy, px[j * 3 + 1]);
                float dz = __fsub_rn(cz, px[j * 3 + 2]);
                float d2 = __fadd_rn(__fadd_rn(__fmul_rn(dx, dx), __fmul_rn(dy, dy)),
                                     __fmul_rn(dz, dz));
                pred = (d2 < r2);
            }
            unsigned m = __ballot_sync(0xffffffffu, pred);
            if (first < 0 && m) first = base + __ffs(m) - 1;
            if (pred) {
                int pos = cnt + __popc(m & ((1u << tid) - 1u));
                if (pos < K) sIdx[pos] = j;
            }
            cnt += __popc(m);
            if (cnt >= K) break;
        }
        int fillv = (first < 0) ? 0 : first;
        for (int k = cnt + tid; k < K; k += 32) sIdx[k] = fillv;
    }
    __syncthreads();

    const int C = 3 + Cf;
    const size_t SK = (size_t)S * K;
    const size_t pbase = (size_t)s * K;
    for (int e = tid; e < C * K; e += blockDim.x) {
        int ch = e / K, k = e - ch * K;
        int j = sIdx[k];
        float v;
        if (ch == 0)      v = __fsub_rn(px[j * 3 + 0], cx);
        else if (ch == 1) v = __fsub_rn(px[j * 3 + 1], cy);
        else if (ch == 2) v = __fsub_rn(px[j * 3 + 2], cz);
        else              v = feats[((size_t)b * Cf + (ch - 3)) * N + j];
        grp[((size_t)b * C + ch) * SK + pbase + k] = v;
    }
}

// ---------------- SA1 layer1: 9 -> 64 streaming conv + BN + ReLU ----------------
__global__ void conv9_kernel(const float* __restrict__ x, const float* __restrict__ W,
                             const float* __restrict__ g, const float* __restrict__ bi,
                             float* __restrict__ out, int P) {
    __shared__ float ws[64 * 9];
    __shared__ float gs[64], bs[64];
    const int tid = threadIdx.x;
    if (tid < 64) { gs[tid] = g[tid]; bs[tid] = bi[tid]; }
    for (int e = tid; e < 576; e += 256) ws[e] = W[e];
    __syncthreads();

    const int b = blockIdx.y;
    const int p = blockIdx.x * 256 + tid;
    const float* xb = x + (size_t)b * 9 * P;
    float xv[9];
#pragma unroll
    for (int c = 0; c < 9; c++) xv[c] = xb[(size_t)c * P + p];
    float* ob = out + (size_t)b * 64 * P;
#pragma unroll 8
    for (int o = 0; o < 64; o++) {
        float a = 0.f;
#pragma unroll
        for (int c = 0; c < 9; c++) a = fmaf(ws[o * 9 + c], xv[c], a);
        ob[(size_t)o * P + p] = fmaxf(fmaf(a, gs[o], bs[o]), 0.f);
    }
}

// ---------------- f32x2 SGEMM: 128o x 128p tile, K-chunk 8, double-buffered --------
// x: [B, Cin, P] (col = point). Wd: duplicated weights [Cin][2*Cout].
// MAXPOOL=0: out[b,o,p] = relu(g*acc+b). MAXPOOL=1: out[b,o,s] = max_k relu(...).
// Thread layout: 8 warps = 4(o) x 2(p); warp tile 32o x 64p; thread 8o x 8p.
template <int MAXPOOL>
__global__ __launch_bounds__(256, 2) void sgemm_kernel(
    const float* __restrict__ x, const float* __restrict__ Wd,
    const float* __restrict__ g, const float* __restrict__ bi,
    float* __restrict__ out, int Cin, int Cout, int P, int S, int K) {
    __shared__ float ws[2][8][264];  // duplicated: row k holds Wd slice, 256 words + pad 8
    __shared__ float xs[2][8][128];

    const int b = blockIdx.z;
    const int o0 = blockIdx.y * 128;
    const int p0 = blockIdx.x * 128;
    const int tid = threadIdx.x;
    const int w = tid >> 5, l = tid & 31;
    const int warp_o = (w & 3) * 32;
    const int warp_p = (w >> 2) * 64;
    const int ofs = warp_o + ((l >> 3) << 2);  // thread o-frag base (and +16)
    const int pfs = warp_p + ((l & 7) << 2);   // thread p-frag base (and +32)

    const float* xb = x + (size_t)b * Cin * P;
    const int twoC = 2 * Cout;

    unsigned long long acc2[8][4];
#pragma unroll
    for (int i = 0; i < 8; i++)
#pragma unroll
        for (int j = 0; j < 4; j++) acc2[i][j] = 0ull;

    const int nch = (Cin + 7) >> 3;

    // ---- staging lambda (cp.async) ----
    auto stage = [&](int c0, int buf) {
        // ws: 8 k-rows x 256 duplicated words = 512 x 16B; 2 cp16 per thread
#pragma unroll
        for (int i = 0; i < 2; i++) {
            int e = tid + i * 256;
            int k = e >> 6, w4 = (e & 63) * 4;
            int cc = c0 + k;
            bool v = cc < Cin;
            const float* src = v ? (Wd + (size_t)cc * twoC + 2 * o0 + w4) : Wd;
            cp16(smem_u32(&ws[buf][k][w4]), src, v);
        }
        // xs: 8 k-rows x 128 words = 256 x 16B; 1 cp16 per thread
        {
            int k = tid >> 5, p4 = (tid & 31) * 4;
            int cc = c0 + k;
            bool v = (cc < Cin) && (p0 + p4 < P);
            const float* src = v ? (xb + (size_t)cc * P + p0 + p4) : xb;
            cp16(smem_u32(&xs[buf][k][p4]), src, v);
        }
    };

    stage(0, 0);
    cp_commit();

    for (int c = 0; c < nch; c++) {
        if (c + 1 < nch) {
            stage((c + 1) * 8, (c + 1) & 1);
            cp_commit();
            cp_wait<1>();
        } else {
            cp_wait<0>();
        }
        __syncthreads();

        const float(*wsb)[264] = ws[c & 1];
        const float(*xsb)[128] = xs[c & 1];
#pragma unroll
        for (int k = 0; k < 8; k++) {
            ulonglong2 a01 = *(const ulonglong2*)&wsb[k][2 * ofs];
            ulonglong2 a23 = *(const ulonglong2*)&wsb[k][2 * ofs + 4];
            ulonglong2 a45 = *(const ulonglong2*)&wsb[k][2 * (ofs + 16)];
            ulonglong2 a67 = *(const ulonglong2*)&wsb[k][2 * (ofs + 16) + 4];
            ulonglong2 b01 = *(const ulonglong2*)&xsb[k][pfs];
            ulonglong2 b23 = *(const ulonglong2*)&xsb[k][pfs + 32];
            unsigned long long av[8] = {a01.x, a01.y, a23.x, a23.y,
                                        a45.x, a45.y, a67.x, a67.y};
            unsigned long long bv[4] = {b01.x, b01.y, b23.x, b23.y};
#pragma unroll
            for (int i = 0; i < 8; i++)
#pragma unroll
                for (int j = 0; j < 4; j++) fma2(acc2[i][j], av[i], bv[j]);
        }
        __syncthreads();
    }

    // ---- epilogue ----
#pragma unroll
    for (int i = 0; i < 8; i++) {
        int o = o0 + ofs + ((i < 4) ? i : (12 + i));
        float gv = g[o], bb = bi[o];
        float vf[8];
#pragma unroll
        for (int j = 0; j < 4; j++) {
            vf[2 * j]     = fmaxf(fmaf(u64lo(acc2[i][j]), gv, bb), 0.f);
            vf[2 * j + 1] = fmaxf(fmaf(u64hi(acc2[i][j]), gv, bb), 0.f);
        }
        if (MAXPOOL == 0) {
            float* ob = out + (size_t)b * Cout * P + (size_t)o * P;
            if (p0 + pfs < P) {
                float4 v0 = make_float4(vf[0], vf[1], vf[2], vf[3]);
                *(float4*)&ob[p0 + pfs] = v0;
            }
            if (p0 + pfs + 32 < P) {
                float4 v1 = make_float4(vf[4], vf[5], vf[6], vf[7]);
                *(float4*)&ob[p0 + pfs + 32] = v1;
            }
        } else {
            if (K == 64) {
                float m = vf[0];
#pragma unroll
                for (int j = 1; j < 8; j++) m = fmaxf(m, vf[j]);
#pragma unroll
                for (int off = 1; off < 8; off <<= 1)
                    m = fmaxf(m, __shfl_xor_sync(0xffffffffu, m, off));
                if ((l & 7) == 0) {
                    int pg = p0 + warp_p;
                    if (pg < P)
                        out[((size_t)b * Cout + o) * S + (pg >> 6)] = m;
                }
            } else {  // K == 32
                float m0 = fmaxf(fmaxf(vf[0], vf[1]), fmaxf(vf[2], vf[3]));
                float m1 = fmaxf(fmaxf(vf[4], vf[5]), fmaxf(vf[6], vf[7]));
#pragma unroll
                for (int off = 1; off < 8; off <<= 1) {
                    m0 = fmaxf(m0, __shfl_xor_sync(0xffffffffu, m0, off));
                    m1 = fmaxf(m1, __shfl_xor_sync(0xffffffffu, m1, off));
                }
                if ((l & 7) == 0) {
                    int pg = p0 + warp_p;
                    if (pg < P)
                        out[((size_t)b * Cout + o) * S + (pg >> 5)] = m0;
                    if (pg + 32 < P)
                        out[((size_t)b * Cout + o) * S + ((pg + 32) >> 5)] = m1;
                }
            }
        }
    }
}

// ---------------- dense layer on [B, Cin] vectors (classifier head) ----------------
__global__ void dense_kernel(const float* __restrict__ x, const float* __restrict__ W,
                             const float* __restrict__ g, const float* __restrict__ bi,
                             float* __restrict__ out, int Cin, int Cout, int do_relu) {
    const int b = blockIdx.x;
    const int o = blockIdx.y * 8 + (threadIdx.x >> 5);
    const int lane = threadIdx.x & 31;
    if (o >= Cout) return;
    const float* xb = x + (size_t)b * Cin;
    float acc = 0.f;
    for (int c = lane; c < Cin; c += 32)
        acc = fmaf(W[(size_t)o * Cin + c], xb[c], acc);
#pragma unroll
    for (int off = 16; off; off >>= 1)
        acc += __shfl_xor_sync(0xffffffffu, acc, off);
    if (lane == 0) {
        float v = g ? fmaf(acc, g[o], bi[o]) : (acc + bi[o]);
        if (do_relu) v = fmaxf(v, 0.f);
        out[(size_t)b * Cout + o] = v;
    }
}

// ---------------- launch ----------------
extern "C" void kernel_launch(void* const* d_in, const int* in_sizes, int n_in,
                              void* d_out, int out_size) {
    const float* pc = (const float*)d_in[0];
    const float* saw[3][2];
    const float* sag[3][2];
    const float* sab[3][2];
    for (int sm = 0; sm < 3; sm++)
        for (int l = 0; l < 2; l++) {
            int base = 1 + sm * 6 + l * 3;
            saw[sm][l] = (const float*)d_in[base + 0];
            sag[sm][l] = (const float*)d_in[base + 1];
            sab[sm][l] = (const float*)d_in[base + 2];
        }
    const float* clsw[4];
    const float* clsg[3];
    const float* clsb[4];
    for (int l = 0; l < 3; l++) {
        clsw[l] = (const float*)d_in[19 + l * 3 + 0];
        clsg[l] = (const float*)d_in[19 + l * 3 + 1];
        clsb[l] = (const float*)d_in[19 + l * 3 + 2];
    }
    clsw[3] = (const float*)d_in[28];
    clsb[3] = (const float*)d_in[29];

    float *xyz1, *feat1, *xyz2, *grp1, *h1, *feat2, *xyz3, *grp2, *h2, *feat3;
    float *xyz4, *grp3, *h3, *feat4, *c1, *c2, *c3, *wdup;
    int *sidx1, *sidx2, *sidx3;
    cudaGetSymbolAddress((void**)&xyz1, g_xyz1);
    cudaGetSymbolAddress((void**)&feat1, g_feat1);
    cudaGetSymbolAddress((void**)&sidx1, g_sidx1);
    cudaGetSymbolAddress((void**)&xyz2, g_xyz2);
    cudaGetSymbolAddress((void**)&grp1, g_grp1);
    cudaGetSymbolAddress((void**)&h1, g_h1);
    cudaGetSymbolAddress((void**)&feat2, g_feat2);
    cudaGetSymbolAddress((void**)&sidx2, g_sidx2);
    cudaGetSymbolAddress((void**)&xyz3, g_xyz3);
    cudaGetSymbolAddress((void**)&grp2, g_grp2);
    cudaGetSymbolAddress((void**)&h2, g_h2);
    cudaGetSymbolAddress((void**)&feat3, g_feat3);
    cudaGetSymbolAddress((void**)&sidx3, g_sidx3);
    cudaGetSymbolAddress((void**)&xyz4, g_xyz4);
    cudaGetSymbolAddress((void**)&grp3, g_grp3);
    cudaGetSymbolAddress((void**)&h3, g_h3);
    cudaGetSymbolAddress((void**)&feat4, g_feat4);
    cudaGetSymbolAddress((void**)&c1, g_c1);
    cudaGetSymbolAddress((void**)&c2, g_c2);
    cudaGetSymbolAddress((void**)&c3, g_c3);
    cudaGetSymbolAddress((void**)&wdup, g_wdup);

    // weight duplication (graph-resident; deterministic)
    dup_weights_kernel<<<(64 * 128 + 255) / 256, 256>>>(saw[0][1], wdup + WD0, 64, 128);
    dup_weights_kernel<<<(131 * 128 + 255) / 256, 256>>>(saw[1][0], wdup + WD1, 131, 128);
    dup_weights_kernel<<<(128 * 256 + 255) / 256, 256>>>(saw[1][1], wdup + WD2, 128, 256);
    dup_weights_kernel<<<(259 * 512 + 255) / 256, 256>>>(saw[2][0], wdup + WD3, 259, 512);
    dup_weights_kernel<<<(512 * 1024 + 255) / 256, 256>>>(saw[2][1], wdup + WD4, 512, 1024);

    // split
    split_kernel<<<(BB * NPTS + 255) / 256, 256>>>(pc, xyz1, feat1);

    // ---- SA1: N=4096 -> S=512, K=32, r=0.1, C: 9 -> 64 -> 128 ----
    fps_kernel<<<BB, 1024>>>(xyz1, NPTS, 512, sidx1);
    bq_group_kernel<<<dim3(512, BB), 256>>>(xyz1, sidx1, feat1, xyz2, grp1,
                                            NPTS, 512, 32, 6, (float)(0.1 * 0.1));
    conv9_kernel<<<dim3(512 * 32 / 256, BB), 256>>>(
        grp1, saw[0][0], sag[0][0], sab[0][0], h1, 512 * 32);
    sgemm_kernel<1><<<dim3(16384 / 128, 1, BB), 256>>>(
        h1, wdup + WD0, sag[0][1], sab[0][1], feat2, 64, 128, 16384, 512, 32);

    // ---- SA2: N=512 -> S=64, K=64, r=0.2, C: 131 -> 128 -> 256 ----
    fps_kernel<<<BB, 1024>>>(xyz2, 512, 64, sidx2);
    bq_group_kernel<<<dim3(64, BB), 256>>>(xyz2, sidx2, feat2, xyz3, grp2,
                                           512, 64, 64, 128, (float)(0.2 * 0.2));
    sgemm_kernel<0><<<dim3(4096 / 128, 1, BB), 256>>>(
        grp2, wdup + WD1, sag[1][0], sab[1][0], h2, 131, 128, 4096, 0, 0);
    sgemm_kernel<1><<<dim3(4096 / 128, 2, BB), 256>>>(
        h2, wdup + WD2, sag[1][1], sab[1][1], feat3, 128, 256, 4096, 64, 64);

    // ---- SA3: N=64 -> S=1, K=64, r=0.4, C: 259 -> 512 -> 1024 ----
    fps_kernel<<<BB, 1024>>>(xyz3, 64, 1, sidx3);
    bq_group_kernel<<<dim3(1, BB), 256>>>(xyz3, sidx3, feat3, xyz4, grp3,
                                          64, 1, 64, 256, (float)(0.4 * 0.4));
    sgemm_kernel<0><<<dim3(1, 4, BB), 256>>>(
        grp3, wdup + WD3, sag[2][0], sab[2][0], h3, 259, 512, 64, 0, 0);
    sgemm_kernel<1><<<dim3(1, 8, BB), 256>>>(
        h3, wdup + WD4, sag[2][1], sab[2][1], feat4, 512, 1024, 64, 1, 64);

    // ---- classifier head on [B, 1024] ----
    dense_kernel<<<dim3(BB, 1024 / 8), 256>>>(feat4, clsw[0], clsg[0], clsb[0], c1, 1024, 1024, 1);
    dense_kernel<<<dim3(BB, 512 / 8), 256>>>(c1, clsw[1], clsg[1], clsb[1], c2, 1024, 512, 1);
    dense_kernel<<<dim3(BB, 128 / 8), 256>>>(c2, clsw[2], clsg[2], clsb[2], c3, 512, 128, 1);
    dense_kernel<<<dim3(BB, (63 + 7) / 8), 256>>>(c3, clsw[3], nullptr, clsb[3],
                                                  (float*)d_out, 128, 63, 0);
}